// round 2
// baseline (speedup 1.0000x reference)
#include <cuda_runtime.h>
#include <cstdint>
#include <cstddef>

// ---------------------------------------------------------------------------
// myVMLSTM: T=256, B=64, D=1024, H=1024, R=256
//   precompute:  d2_x/d2_h (diag - lowrank-diag correction), Gx = (X u_x) w_x^T + ...
//   recurrence:  persistent kernel, 128 CTAs, grid barrier, h/c in registers
// ---------------------------------------------------------------------------

constexpr int T   = 256;
constexpr int Bsz = 64;
constexpr int D   = 1024;
constexpr int H   = 1024;
constexpr int R   = 256;
constexpr int G4H = 4 * H;          // 4096
constexpr int TB  = T * Bsz;        // 16384
constexpr int NB  = 128;            // persistent blocks (all co-resident, <=148 SMs)
constexpr int NTH = 256;

// scratch (static __device__ arrays: allocation-free per harness rules)
__device__ float g_P [(size_t)TB * R];     // 16 MB   X @ u_x
__device__ float g_Gx[(size_t)TB * G4H];   // 256 MB  precomputed input-path gates
__device__ float g_d2x[G4H];
__device__ float g_d2h[G4H];
__device__ float g_h [Bsz * H];            // current hidden state
__device__ float g_p [Bsz * R];            // per-step h @ u_h
__device__ unsigned g_count;
__device__ unsigned g_phase;

// ---------------------------------------------------------------------------
// grid barrier (all NB blocks resident by construction)
// ---------------------------------------------------------------------------
__device__ __forceinline__ void gbar() {
    __threadfence();
    __syncthreads();
    if (threadIdx.x == 0) {
        unsigned my = *(volatile unsigned*)&g_phase;
        if (atomicAdd(&g_count, 1u) == NB - 1) {
            g_count = 0u;
            __threadfence();
            *(volatile unsigned*)&g_phase = my + 1u;
        } else {
            while (*(volatile unsigned*)&g_phase == my) { }
        }
        __threadfence();
    }
    __syncthreads();
}

// ---------------------------------------------------------------------------
// prep: d2_x[n] = dia_x[n%H] - sum_r u_x[d,r] w_x[n,r]   (same for h), copy h0
// ---------------------------------------------------------------------------
__global__ void prep_kernel(const float* __restrict__ u_x, const float* __restrict__ w_x,
                            const float* __restrict__ dia_x,
                            const float* __restrict__ u_h, const float* __restrict__ w_h,
                            const float* __restrict__ dia_h,
                            const float* __restrict__ h0)
{
    int n = blockIdx.x * blockDim.x + threadIdx.x;   // 0..8191
    const float *u, *w, *dia; float* o; int idx;
    if (n < G4H) { u = u_x; w = w_x; dia = dia_x; o = g_d2x; idx = n; }
    else         { u = u_h; w = w_h; dia = dia_h; o = g_d2h; idx = n - G4H; }
    int d = idx & (H - 1);
    const float4* ur = reinterpret_cast<const float4*>(u + (size_t)d   * R);
    const float4* wr = reinterpret_cast<const float4*>(w + (size_t)idx * R);
    float s = 0.f;
    #pragma unroll 8
    for (int k = 0; k < R / 4; ++k) {
        float4 a = ur[k], b = wr[k];
        s += a.x * b.x + a.y * b.y + a.z * b.z + a.w * b.w;
    }
    o[idx] = dia[d] - s;
    for (int i = n; i < Bsz * H; i += 8192) g_h[i] = h0[i];
}

// ---------------------------------------------------------------------------
// tiled fp32 GEMM, C[M,N] = sum_k A[m,k] * B(k,n)
//   B_IS_NK: B stored [N,K] row-major (NT, for w_x) else [K,N] (NN, for u_x)
//   EPI:     C += X[m, n&1023]*d2[n] + bias[n]
// ---------------------------------------------------------------------------
template<bool B_IS_NK, bool EPI>
__global__ void __launch_bounds__(256) gemm_k(
    const float* __restrict__ A, const float* __restrict__ Bm, float* __restrict__ C,
    int M, int N, int K,
    const float* __restrict__ X, const float* __restrict__ d2v, const float* __restrict__ bias)
{
    constexpr int BM = 128, BN = 128, BK = 16;
    __shared__ float As[BK][BM];
    __shared__ float Bs[BK][BN];
    const int tid = threadIdx.x;
    const int m0 = blockIdx.y * BM, n0 = blockIdx.x * BN;
    const int tx = tid & 15, ty = tid >> 4;
    float acc[8][8];
    #pragma unroll
    for (int i = 0; i < 8; ++i)
        #pragma unroll
        for (int j = 0; j < 8; ++j) acc[i][j] = 0.f;

    for (int k0 = 0; k0 < K; k0 += BK) {
        #pragma unroll
        for (int q = 0; q < 2; ++q) {              // A tile, transposed store
            int f = tid * 2 + q;
            int row = f >> 2, kq = f & 3;
            float4 v = *reinterpret_cast<const float4*>(
                &A[(size_t)(m0 + row) * K + k0 + kq * 4]);
            As[kq * 4 + 0][row] = v.x;
            As[kq * 4 + 1][row] = v.y;
            As[kq * 4 + 2][row] = v.z;
            As[kq * 4 + 3][row] = v.w;
        }
        if constexpr (B_IS_NK) {
            #pragma unroll
            for (int q = 0; q < 2; ++q) {
                int f = tid * 2 + q;
                int row = f >> 2, kq = f & 3;
                float4 v = *reinterpret_cast<const float4*>(
                    &Bm[(size_t)(n0 + row) * K + k0 + kq * 4]);
                Bs[kq * 4 + 0][row] = v.x;
                Bs[kq * 4 + 1][row] = v.y;
                Bs[kq * 4 + 2][row] = v.z;
                Bs[kq * 4 + 3][row] = v.w;
            }
        } else {
            #pragma unroll
            for (int q = 0; q < 2; ++q) {
                int f = tid * 2 + q;               // float4 index 0..511
                int kr = f >> 5, nc = f & 31;
                *reinterpret_cast<float4*>(&Bs[kr][nc * 4]) =
                    *reinterpret_cast<const float4*>(
                        &Bm[(size_t)(k0 + kr) * N + n0 + nc * 4]);
            }
        }
        __syncthreads();
        #pragma unroll
        for (int k = 0; k < BK; ++k) {
            float af[8], bf[8];
            *reinterpret_cast<float4*>(af)     = *reinterpret_cast<float4*>(&As[k][ty * 8]);
            *reinterpret_cast<float4*>(af + 4) = *reinterpret_cast<float4*>(&As[k][ty * 8 + 4]);
            *reinterpret_cast<float4*>(bf)     = *reinterpret_cast<float4*>(&Bs[k][tx * 8]);
            *reinterpret_cast<float4*>(bf + 4) = *reinterpret_cast<float4*>(&Bs[k][tx * 8 + 4]);
            #pragma unroll
            for (int i = 0; i < 8; ++i)
                #pragma unroll
                for (int j = 0; j < 8; ++j)
                    acc[i][j] += af[i] * bf[j];
        }
        __syncthreads();
    }
    #pragma unroll
    for (int i = 0; i < 8; ++i) {
        int m = m0 + ty * 8 + i;
        #pragma unroll
        for (int jj = 0; jj < 2; ++jj) {
            int n = n0 + tx * 8 + jj * 4;
            float4 v;
            v.x = acc[i][jj * 4 + 0];
            v.y = acc[i][jj * 4 + 1];
            v.z = acc[i][jj * 4 + 2];
            v.w = acc[i][jj * 4 + 3];
            if constexpr (EPI) {
                const float* xr = &X[(size_t)m * H];
                v.x += xr[(n + 0) & (H - 1)] * d2v[n + 0] + bias[n + 0];
                v.y += xr[(n + 1) & (H - 1)] * d2v[n + 1] + bias[n + 1];
                v.z += xr[(n + 2) & (H - 1)] * d2v[n + 2] + bias[n + 2];
                v.w += xr[(n + 3) & (H - 1)] * d2v[n + 3] + bias[n + 3];
            }
            *reinterpret_cast<float4*>(&C[(size_t)m * N + n]) = v;
        }
    }
}

// ---------------------------------------------------------------------------
// persistent recurrent kernel
//   block bk: phase1 owns p[:, 2bk..2bk+1]; phase2 owns h[:, 8bk..8bk+7]
//   SMEM: su = u_h 2 cols [2][1024]; swt = w_h 32 rows [32][260] (persistent)
//         sbuf = h stage [64][132] (phase1) / p stage [64][260] (phase2)
// ---------------------------------------------------------------------------
constexpr int SU_F  = 2 * D;                // 2048
constexpr int SW_ST = 260;
constexpr int SW_F  = 32 * SW_ST;           // 8320
constexpr int RED_F = 256;
constexpr int SB_F  = 64 * 260;             // 16640
constexpr int SMEM_F = SU_F + SW_F + RED_F + SB_F;   // 27264 floats
constexpr size_t SMEM_BYTES = (size_t)SMEM_F * 4;    // 109056 B

__global__ void __launch_bounds__(NTH, 1) lstm_rec(
    const float* __restrict__ c0, const float* __restrict__ h0,
    const float* __restrict__ u_h, const float* __restrict__ w_h,
    const float* __restrict__ b_h, float* __restrict__ out, int full_out)
{
    extern __shared__ float sm[];
    float* su   = sm;
    float* swt  = sm + SU_F;
    float* red  = swt + SW_F;
    float* sbuf = red + RED_F;

    const int tid = threadIdx.x;
    const int bk  = blockIdx.x;
    const int r0  = bk * 2;
    const int j0  = bk * 8;

    // persistent SMEM loads (once for all 256 steps)
    for (int i = tid; i < 2 * D; i += NTH) {
        int rl = i >> 10, d = i & (D - 1);
        su[i] = u_h[(size_t)d * R + r0 + rl];          // su[rl*1024 + d]
    }
    for (int i = tid; i < 32 * R; i += NTH) {
        int row = i >> 8, r = i & (R - 1);
        int g = row >> 3, jl = row & 7;
        swt[row * SW_ST + r] = w_h[(size_t)(g * H + j0 + jl) * R + r];
    }

    // per-thread state: this thread owns (b0,j) and (b1,j) forever
    const int jl = tid & 7;
    const int bg = tid >> 3;
    const int b0 = bg * 2, b1 = b0 + 1;
    const int j  = j0 + jl;
    float d2r[4], bhr[4];
    #pragma unroll
    for (int g = 0; g < 4; ++g) {
        d2r[g] = g_d2h[g * H + j];
        bhr[g] = b_h[g * H + j];
    }
    float hr[2], cr[2];
    hr[0] = h0[b0 * H + j]; hr[1] = h0[b1 * H + j];
    cr[0] = c0[b0 * H + j]; cr[1] = c0[b1 * H + j];

    // phase1 thread roles
    const int pb  = tid & 63;
    const int prl = (tid >> 6) & 1;
    const int ph  = tid >> 7;

    __syncthreads();

    for (int t = 0; t < T; ++t) {
        // ---------------- phase 1: p[:, r0:r0+2] = h @ u_h cols ------------
        float4 a4 = make_float4(0.f, 0.f, 0.f, 0.f);
        for (int dt = 0; dt < D; dt += 128) {
            __syncthreads();                               // protect sbuf reuse
            for (int i = tid; i < 64 * 32; i += NTH) {     // stage h[64][128]
                int bb = i >> 5, d4 = i & 31;
                *reinterpret_cast<float4*>(&sbuf[bb * 132 + d4 * 4]) =
                    *reinterpret_cast<const float4*>(&g_h[bb * H + dt + d4 * 4]);
            }
            __syncthreads();
            const float4* hv = reinterpret_cast<const float4*>(&sbuf[pb * 132 + ph * 64]);
            const float4* uv = reinterpret_cast<const float4*>(&su[prl * D + dt + ph * 64]);
            #pragma unroll
            for (int k = 0; k < 16; ++k) {
                float4 hh = hv[k], uu = uv[k];
                a4.x += hh.x * uu.x; a4.y += hh.y * uu.y;
                a4.z += hh.z * uu.z; a4.w += hh.w * uu.w;
            }
        }
        red[tid] = (a4.x + a4.y) + (a4.z + a4.w);
        __syncthreads();
        if (tid < 128)
            g_p[pb * R + r0 + prl] = red[tid] + red[tid + 128];
        gbar();

        // ---------------- phase 2: gates + state update --------------------
        float gx[2][4];
        {
            const float* gp = g_Gx + (size_t)(t * Bsz) * G4H;
            #pragma unroll
            for (int g = 0; g < 4; ++g) {
                gx[0][g] = gp[(size_t)b0 * G4H + g * H + j];
                gx[1][g] = gp[(size_t)b1 * G4H + g * H + j];
            }
        }
        for (int i = tid; i < 64 * 64; i += NTH) {         // stage p[64][256]
            int bb = i >> 6, r4 = i & 63;
            *reinterpret_cast<float4*>(&sbuf[bb * 260 + r4 * 4]) =
                reinterpret_cast<const float4*>(g_p)[i];
        }
        __syncthreads();

        float acc[2][4];
        #pragma unroll
        for (int i = 0; i < 2; ++i)
            #pragma unroll
            for (int g = 0; g < 4; ++g) acc[i][g] = 0.f;
        {
            const float4* p0 = reinterpret_cast<const float4*>(&sbuf[b0 * 260]);
            const float4* p1 = reinterpret_cast<const float4*>(&sbuf[b1 * 260]);
            const float4* w0 = reinterpret_cast<const float4*>(&swt[(0 * 8 + jl) * SW_ST]);
            const float4* w1 = reinterpret_cast<const float4*>(&swt[(1 * 8 + jl) * SW_ST]);
            const float4* w2 = reinterpret_cast<const float4*>(&swt[(2 * 8 + jl) * SW_ST]);
            const float4* w3 = reinterpret_cast<const float4*>(&swt[(3 * 8 + jl) * SW_ST]);
            #pragma unroll 8
            for (int k = 0; k < 64; ++k) {
                float4 x0 = p0[k], x1 = p1[k];
                float4 wa = w0[k];
                acc[0][0] += x0.x*wa.x + x0.y*wa.y + x0.z*wa.z + x0.w*wa.w;
                acc[1][0] += x1.x*wa.x + x1.y*wa.y + x1.z*wa.z + x1.w*wa.w;
                float4 wb = w1[k];
                acc[0][1] += x0.x*wb.x + x0.y*wb.y + x0.z*wb.z + x0.w*wb.w;
                acc[1][1] += x1.x*wb.x + x1.y*wb.y + x1.z*wb.z + x1.w*wb.w;
                float4 wc = w2[k];
                acc[0][2] += x0.x*wc.x + x0.y*wc.y + x0.z*wc.z + x0.w*wc.w;
                acc[1][2] += x1.x*wc.x + x1.y*wc.y + x1.z*wc.z + x1.w*wc.w;
                float4 wd = w3[k];
                acc[0][3] += x0.x*wd.x + x0.y*wd.y + x0.z*wd.z + x0.w*wd.w;
                acc[1][3] += x1.x*wd.x + x1.y*wd.y + x1.z*wd.z + x1.w*wd.w;
            }
        }
        const int bb2[2] = { b0, b1 };
        #pragma unroll
        for (int i = 0; i < 2; ++i) {
            float pi = acc[i][0] + hr[i] * d2r[0] + bhr[0] + gx[i][0];
            float pf = acc[i][1] + hr[i] * d2r[1] + bhr[1] + gx[i][1];
            float po = acc[i][2] + hr[i] * d2r[2] + bhr[2] + gx[i][2];
            float pn = acc[i][3] + hr[i] * d2r[3] + bhr[3] + gx[i][3];
            float ig = 1.f / (1.f + expf(-pi));
            float fg = 1.f / (1.f + expf(-pf));
            float og = 1.f / (1.f + expf(-po));
            float ng = tanhf(pn);
            cr[i] = fg * cr[i] + ig * ng;
            hr[i] = og * tanhf(cr[i]);
            g_h[bb2[i] * H + j] = hr[i];
            out[(size_t)t * (Bsz * H) + bb2[i] * H + j] = hr[i];
        }
        if (t == T - 1 && full_out) {
            #pragma unroll
            for (int i = 0; i < 2; ++i) {
                out[(size_t)T * Bsz * H + bb2[i] * H + j]           = hr[i];
                out[(size_t)T * Bsz * H + Bsz * H + bb2[i] * H + j] = cr[i];
            }
        }
        gbar();
    }
}

// ---------------------------------------------------------------------------
extern "C" void kernel_launch(void* const* d_in, const int* in_sizes, int n_in,
                              void* d_out, int out_size)
{
    const float* x     = (const float*)d_in[0];
    const float* h0    = (const float*)d_in[1];
    const float* c0    = (const float*)d_in[2];
    const float* u_x   = (const float*)d_in[3];
    const float* u_h   = (const float*)d_in[4];
    const float* w_x   = (const float*)d_in[5];
    const float* w_h   = (const float*)d_in[6];
    const float* b_x   = (const float*)d_in[7];
    const float* b_h   = (const float*)d_in[8];
    const float* dia_x = (const float*)d_in[9];
    const float* dia_h = (const float*)d_in[10];
    float* out = (float*)d_out;

    float *pP = nullptr, *pGx = nullptr, *pd2x = nullptr;
    cudaGetSymbolAddress((void**)&pP,   g_P);
    cudaGetSymbolAddress((void**)&pGx,  g_Gx);
    cudaGetSymbolAddress((void**)&pd2x, g_d2x);

    // 1) diag corrections + h init
    prep_kernel<<<32, 256>>>(u_x, w_x, dia_x, u_h, w_h, dia_h, h0);

    // 2) P = X @ u_x      (M=16384, N=256, K=1024; B stored [K,N])
    {
        dim3 grid(R / 128, TB / 128);
        gemm_k<false, false><<<grid, 256>>>(x, u_x, pP, TB, R, D,
                                            nullptr, nullptr, nullptr);
    }
    // 3) Gx = P @ w_x^T + x*d2_x + b_x   (M=16384, N=4096, K=256; B stored [N,K])
    {
        dim3 grid(G4H / 128, TB / 128);
        gemm_k<true, true><<<grid, 256>>>(pP, w_x, pGx, TB, G4H, R,
                                          x, pd2x, b_x);
    }
    // 4) persistent recurrence
    cudaFuncSetAttribute(lstm_rec, cudaFuncAttributeMaxDynamicSharedMemorySize,
                         (int)SMEM_BYTES);
    int full_out = (out_size >= T * Bsz * H + 2 * Bsz * H) ? 1 : 0;
    lstm_rec<<<NB, NTH, SMEM_BYTES>>>(c0, h0, u_h, w_h, b_h, out, full_out);
}

// round 5
// speedup vs baseline: 1.0775x; 1.0775x over previous
#include <cuda_runtime.h>
#include <cstdint>
#include <cstddef>

// ---------------------------------------------------------------------------
// myVMLSTM: T=256, B=64, D=1024, H=1024, R=256
//   precompute:  d2 = diag - lowrank-diag correction; Gx = (X u_x) w_x^T + x*d2 + b
//   recurrence:  persistent kernel, 128 CTAs, 512 thr, grid barrier, FFMA2
// ---------------------------------------------------------------------------

constexpr int T   = 256;
constexpr int Bsz = 64;
constexpr int D   = 1024;
constexpr int H   = 1024;
constexpr int R   = 256;
constexpr int G4H = 4 * H;          // 4096
constexpr int TB  = T * Bsz;        // 16384
constexpr int NB  = 128;            // persistent blocks
constexpr int NTH = 512;

// scratch (static __device__ arrays: allocation-free per harness rules)
__device__ float g_P [(size_t)TB * R];     // 16 MB   X @ u_x
__device__ float g_Gx[(size_t)TB * G4H];   // 256 MB  precomputed input-path gates
__device__ float g_d2x[G4H];
__device__ float g_d2h[G4H];
__device__ float g_h [Bsz * H];            // current hidden state
__device__ float g_p [Bsz * R];            // per-step h @ u_h
__device__ unsigned g_count;
__device__ unsigned g_phase;

// ---------------------------------------------------------------------------
// packed fp32x2 helpers (Blackwell FFMA2 — ptxas never auto-emits this)
// ---------------------------------------------------------------------------
__device__ __forceinline__ void fma2(unsigned long long& acc,
                                     unsigned long long a, unsigned long long b) {
    asm("fma.rn.f32x2 %0, %1, %2, %0;" : "+l"(acc) : "l"(a), "l"(b));
}
__device__ __forceinline__ unsigned long long pack_dup(float a) {
    unsigned long long v;
    asm("mov.b64 %0, {%1, %1};" : "=l"(v) : "f"(a));
    return v;
}
__device__ __forceinline__ float2 unpack2(unsigned long long v) {
    float2 f;
    asm("mov.b64 {%0, %1}, %2;" : "=f"(f.x), "=f"(f.y) : "l"(v));
    return f;
}

// ---------------------------------------------------------------------------
// grid barrier (all NB blocks resident by construction)
// ---------------------------------------------------------------------------
__device__ __forceinline__ void gbar() {
    __threadfence();
    __syncthreads();
    if (threadIdx.x == 0) {
        unsigned my = *(volatile unsigned*)&g_phase;
        if (atomicAdd(&g_count, 1u) == NB - 1) {
            g_count = 0u;
            __threadfence();
            *(volatile unsigned*)&g_phase = my + 1u;
        } else {
            while (*(volatile unsigned*)&g_phase == my) { }
        }
        __threadfence();
    }
    __syncthreads();
}

// ---------------------------------------------------------------------------
// prep: d2[n] = dia[n%H] - sum_r u[d,r] w[n,r]  (x and h), copy h0 -> g_h
// ---------------------------------------------------------------------------
__global__ void prep_kernel(const float* __restrict__ u_x, const float* __restrict__ w_x,
                            const float* __restrict__ dia_x,
                            const float* __restrict__ u_h, const float* __restrict__ w_h,
                            const float* __restrict__ dia_h,
                            const float* __restrict__ h0)
{
    int n = blockIdx.x * blockDim.x + threadIdx.x;   // 0..8191
    const float *u, *w, *dia; float* o; int idx;
    if (n < G4H) { u = u_x; w = w_x; dia = dia_x; o = g_d2x; idx = n; }
    else         { u = u_h; w = w_h; dia = dia_h; o = g_d2h; idx = n - G4H; }
    int d = idx & (H - 1);
    const float4* ur = reinterpret_cast<const float4*>(u + (size_t)d   * R);
    const float4* wr = reinterpret_cast<const float4*>(w + (size_t)idx * R);
    float s = 0.f;
    #pragma unroll 8
    for (int k = 0; k < R / 4; ++k) {
        float4 a = ur[k], b = wr[k];
        s += a.x * b.x + a.y * b.y + a.z * b.z + a.w * b.w;
    }
    o[idx] = dia[d] - s;
    for (int i = n; i < Bsz * H; i += 8192) g_h[i] = h0[i];
}

// ---------------------------------------------------------------------------
// tiled fp32 GEMM (FFMA2 + double-buffered SMEM), C[M,N] = sum_k A[m,k]*B(k,n)
//   B_IS_NK: B stored [N,K] row-major (for w_x) else [K,N] (for u_x)
//   EPI:     C += X[m, n&1023]*d2[n] + bias[n]
// ---------------------------------------------------------------------------
template<bool B_IS_NK, bool EPI>
__global__ void __launch_bounds__(256, 2) gemm_k(
    const float* __restrict__ A, const float* __restrict__ Bm, float* __restrict__ C,
    int M, int N, int K,
    const float* __restrict__ X, const float* __restrict__ d2v, const float* __restrict__ bias)
{
    constexpr int BM = 128, BN = 128, BK = 16;
    __shared__ float As[2][BK][BM];
    __shared__ float Bs[2][BK][BN];
    const int tid = threadIdx.x;
    const int m0 = blockIdx.y * BM, n0 = blockIdx.x * BN;
    const int tx = tid & 15, ty = tid >> 4;

    unsigned long long acc2[8][4];
    #pragma unroll
    for (int i = 0; i < 8; ++i)
        #pragma unroll
        for (int j = 0; j < 4; ++j) acc2[i][j] = 0ull;

    float4 ra[2], rb[2];

    auto ldg_tiles = [&](int k0) {
        #pragma unroll
        for (int q = 0; q < 2; ++q) {
            int f = tid * 2 + q;
            { int row = f >> 2, kq = f & 3;
              ra[q] = *reinterpret_cast<const float4*>(
                  &A[(size_t)(m0 + row) * K + k0 + kq * 4]); }
            if constexpr (B_IS_NK) {
                int row = f >> 2, kq = f & 3;
                rb[q] = *reinterpret_cast<const float4*>(
                    &Bm[(size_t)(n0 + row) * K + k0 + kq * 4]);
            } else {
                int kr = f >> 5, nc = f & 31;
                rb[q] = *reinterpret_cast<const float4*>(
                    &Bm[(size_t)(k0 + kr) * N + n0 + nc * 4]);
            }
        }
    };
    auto sts_tiles = [&](int buf) {
        #pragma unroll
        for (int q = 0; q < 2; ++q) {
            int f = tid * 2 + q;
            { int row = f >> 2, kq = f & 3;
              As[buf][kq * 4 + 0][row] = ra[q].x;
              As[buf][kq * 4 + 1][row] = ra[q].y;
              As[buf][kq * 4 + 2][row] = ra[q].z;
              As[buf][kq * 4 + 3][row] = ra[q].w; }
            if constexpr (B_IS_NK) {
                int row = f >> 2, kq = f & 3;
                Bs[buf][kq * 4 + 0][row] = rb[q].x;
                Bs[buf][kq * 4 + 1][row] = rb[q].y;
                Bs[buf][kq * 4 + 2][row] = rb[q].z;
                Bs[buf][kq * 4 + 3][row] = rb[q].w;
            } else {
                int kr = f >> 5, nc = f & 31;
                *reinterpret_cast<float4*>(&Bs[buf][kr][nc * 4]) = rb[q];
            }
        }
    };

    ldg_tiles(0);
    sts_tiles(0);
    __syncthreads();

    const int nIter = K / BK;
    for (int it = 0; it < nIter; ++it) {
        const int cur = it & 1;
        if (it + 1 < nIter) ldg_tiles((it + 1) * BK);
        #pragma unroll
        for (int k = 0; k < BK; ++k) {
            float af[8];
            *reinterpret_cast<float4*>(af)     =
                *reinterpret_cast<const float4*>(&As[cur][k][ty * 8]);
            *reinterpret_cast<float4*>(af + 4) =
                *reinterpret_cast<const float4*>(&As[cur][k][ty * 8 + 4]);
            ulonglong2 b01 = *reinterpret_cast<const ulonglong2*>(&Bs[cur][k][tx * 8]);
            ulonglong2 b23 = *reinterpret_cast<const ulonglong2*>(&Bs[cur][k][tx * 8 + 4]);
            #pragma unroll
            for (int i = 0; i < 8; ++i) {
                unsigned long long ai = pack_dup(af[i]);
                fma2(acc2[i][0], ai, b01.x);
                fma2(acc2[i][1], ai, b01.y);
                fma2(acc2[i][2], ai, b23.x);
                fma2(acc2[i][3], ai, b23.y);
            }
        }
        if (it + 1 < nIter) sts_tiles(cur ^ 1);
        __syncthreads();
    }

    #pragma unroll
    for (int i = 0; i < 8; ++i) {
        int m = m0 + ty * 8 + i;
        float vf[8];
        #pragma unroll
        for (int jp = 0; jp < 4; ++jp) {
            float2 f = unpack2(acc2[i][jp]);
            vf[jp * 2] = f.x; vf[jp * 2 + 1] = f.y;
        }
        #pragma unroll
        for (int jj = 0; jj < 2; ++jj) {
            int n = n0 + tx * 8 + jj * 4;
            float4 v;
            v.x = vf[jj * 4 + 0]; v.y = vf[jj * 4 + 1];
            v.z = vf[jj * 4 + 2]; v.w = vf[jj * 4 + 3];
            if constexpr (EPI) {
                const float* xr = &X[(size_t)m * H];
                v.x += xr[(n + 0) & (H - 1)] * d2v[n + 0] + bias[n + 0];
                v.y += xr[(n + 1) & (H - 1)] * d2v[n + 1] + bias[n + 1];
                v.z += xr[(n + 2) & (H - 1)] * d2v[n + 2] + bias[n + 2];
                v.w += xr[(n + 3) & (H - 1)] * d2v[n + 3] + bias[n + 3];
            }
            *reinterpret_cast<float4*>(&C[(size_t)m * N + n]) = v;
        }
    }
}

// ---------------------------------------------------------------------------
// persistent recurrent kernel, 128 CTAs x 512 threads
//   phase1: CTA (rb=bk&15, bb=bk>>4) computes p[8 b-rows, 16 r-cols];
//           u_h slice (16 cols) persistent in SMEM; only 8 h-rows read/step
//   phase2: CTA bk owns h cols [8bk..8bk+8); thread = (batch b2, col jl2)
// ---------------------------------------------------------------------------
constexpr int SU_ST = 1028;                     // pad vs bank conflicts
constexpr int SU_F  = 16 * SU_ST;               // 16448
constexpr int SW_ST = 260;
constexpr int SW_F  = 32 * SW_ST;               // 8320
constexpr int RED_F = 512;
constexpr int SB_F  = 64 * 260;                 // 16640
constexpr int SMEM_F = SU_F + SW_F + RED_F + SB_F;   // 41920 floats
constexpr size_t SMEM_BYTES = (size_t)SMEM_F * 4;    // 167680 B

__global__ void __launch_bounds__(NTH, 1) lstm_rec(
    const float* __restrict__ c0, const float* __restrict__ h0,
    const float* __restrict__ u_h, const float* __restrict__ w_h,
    const float* __restrict__ b_h, float* __restrict__ out, int full_out)
{
    extern __shared__ float sm[];
    float* su   = sm;                 // [16][1028] this CTA's u_h columns
    float* swt  = sm + SU_F;          // [32][260]  this CTA's w_h rows (4g x 8j)
    float* red  = swt + SW_F;         // [512]
    float* sbuf = red + RED_F;        // phase1: h stage [8][1028]; phase2: p [64][260]

    const int tid = threadIdx.x;
    const int bk  = blockIdx.x;

    // phase1 roles
    const int rb  = bk & 15,  bb = bk >> 4;
    const int r_l = tid & 15, b_l = (tid >> 4) & 7, q = tid >> 7;
    // phase2 roles
    const int jl2 = tid & 7,  b2 = tid >> 3;
    const int j   = bk * 8 + jl2;

    // persistent SMEM (once for all 256 steps)
    for (int i = tid; i < 16 * 1024; i += NTH) {
        int rl = i >> 10, d = i & 1023;
        su[rl * SU_ST + d] = u_h[(size_t)d * R + rb * 16 + rl];
    }
    for (int i = tid; i < 32 * 256; i += NTH) {
        int row = i >> 8, r = i & 255;
        int g = row >> 3, jj = row & 7;
        swt[row * SW_ST + r] = w_h[(size_t)(g * H + bk * 8 + jj) * R + r];
    }

    // per-thread state (b2, j) for all 256 steps
    float d2r[4], bhr[4];
    #pragma unroll
    for (int g = 0; g < 4; ++g) {
        d2r[g] = g_d2h[g * H + j];
        bhr[g] = b_h[g * H + j];
    }
    float hr = h0[b2 * H + j];
    float cr = c0[b2 * H + j];
    __syncthreads();

    for (int t = 0; t < T; ++t) {
        // ------------- phase 1: p[8b,16r] = h[8b,:] @ u_h[:,16r] -----------
        for (int i = tid; i < 8 * 256; i += NTH) {          // stage 8 h rows
            int row = i >> 8, c = i & 255;
            *reinterpret_cast<float4*>(&sbuf[row * SU_ST + c * 4]) =
                __ldcg(reinterpret_cast<const float4*>(
                    &g_h[(bb * 8 + row) * H + c * 4]));
        }
        __syncthreads();
        {
            unsigned long long a0 = 0ull, a1 = 0ull;
            const ulonglong2* hp =
                reinterpret_cast<const ulonglong2*>(&sbuf[b_l * SU_ST + q * 256]);
            const ulonglong2* up =
                reinterpret_cast<const ulonglong2*>(&su[r_l * SU_ST + q * 256]);
            #pragma unroll 8
            for (int k = 0; k < 64; ++k) {
                ulonglong2 hh = hp[k], uu = up[k];
                fma2(a0, hh.x, uu.x);
                fma2(a1, hh.y, uu.y);
            }
            float2 f0 = unpack2(a0), f1 = unpack2(a1);
            red[tid] = (f0.x + f0.y) + (f1.x + f1.y);
        }
        __syncthreads();
        if (tid < 128) {
            float s = red[tid] + red[tid + 128] + red[tid + 256] + red[tid + 384];
            int b = bb * 8 + (tid >> 4), r = rb * 16 + (tid & 15);
            __stcg(&g_p[b * R + r], s);
        }
        gbar();

        // ------------- phase 2: gates + state update -----------------------
        const float* gp = g_Gx + (size_t)t * (Bsz * G4H) + (size_t)b2 * G4H + j;
        float gx0 = __ldcs(gp);
        float gx1 = __ldcs(gp + H);
        float gx2 = __ldcs(gp + 2 * H);
        float gx3 = __ldcs(gp + 3 * H);

        for (int i = tid; i < 64 * 64; i += NTH) {          // stage p [64][256]
            int bbx = i >> 6, c = i & 63;
            *reinterpret_cast<float4*>(&sbuf[bbx * 260 + c * 4]) =
                __ldcg(reinterpret_cast<const float4*>(g_p) + i);
        }
        __syncthreads();

        unsigned long long A0 = 0, A1 = 0, B0 = 0, B1 = 0,
                           C0 = 0, C1 = 0, D0 = 0, D1 = 0;
        {
            const ulonglong2* pp =
                reinterpret_cast<const ulonglong2*>(&sbuf[b2 * 260]);
            const ulonglong2* w0 =
                reinterpret_cast<const ulonglong2*>(&swt[(0 * 8 + jl2) * SW_ST]);
            const ulonglong2* w1 =
                reinterpret_cast<const ulonglong2*>(&swt[(1 * 8 + jl2) * SW_ST]);
            const ulonglong2* w2 =
                reinterpret_cast<const ulonglong2*>(&swt[(2 * 8 + jl2) * SW_ST]);
            const ulonglong2* w3 =
                reinterpret_cast<const ulonglong2*>(&swt[(3 * 8 + jl2) * SW_ST]);
            #pragma unroll 8
            for (int k = 0; k < 64; ++k) {
                ulonglong2 pv = pp[k];
                ulonglong2 w;
                w = w0[k]; fma2(A0, pv.x, w.x); fma2(A1, pv.y, w.y);
                w = w1[k]; fma2(B0, pv.x, w.x); fma2(B1, pv.y, w.y);
                w = w2[k]; fma2(C0, pv.x, w.x); fma2(C1, pv.y, w.y);
                w = w3[k]; fma2(D0, pv.x, w.x); fma2(D1, pv.y, w.y);
            }
        }
        float2 fa0 = unpack2(A0), fa1 = unpack2(A1);
        float2 fb0 = unpack2(B0), fb1 = unpack2(B1);
        float2 fc0 = unpack2(C0), fc1 = unpack2(C1);
        float2 fd0 = unpack2(D0), fd1 = unpack2(D1);
        float pi = (fa0.x + fa0.y) + (fa1.x + fa1.y) + hr * d2r[0] + bhr[0] + gx0;
        float pf = (fb0.x + fb0.y) + (fb1.x + fb1.y) + hr * d2r[1] + bhr[1] + gx1;
        float po = (fc0.x + fc0.y) + (fc1.x + fc1.y) + hr * d2r[2] + bhr[2] + gx2;
        float pn = (fd0.x + fd0.y) + (fd1.x + fd1.y) + hr * d2r[3] + bhr[3] + gx3;

        float ig = 1.f / (1.f + expf(-pi));
        float fg = 1.f / (1.f + expf(-pf));
        float og = 1.f / (1.f + expf(-po));
        float ng = tanhf(pn);
        cr = fg * cr + ig * ng;
        hr = og * tanhf(cr);

        __stcg(&g_h[b2 * H + j], hr);
        __stcs(&out[(size_t)t * (Bsz * H) + b2 * H + j], hr);
        if (t == T - 1 && full_out) {
            out[(size_t)T * Bsz * H + b2 * H + j]           = hr;
            out[(size_t)T * Bsz * H + Bsz * H + b2 * H + j] = cr;
        }
        gbar();
    }
}

// ---------------------------------------------------------------------------
extern "C" void kernel_launch(void* const* d_in, const int* in_sizes, int n_in,
                              void* d_out, int out_size)
{
    const float* x     = (const float*)d_in[0];
    const float* h0    = (const float*)d_in[1];
    const float* c0    = (const float*)d_in[2];
    const float* u_x   = (const float*)d_in[3];
    const float* u_h   = (const float*)d_in[4];
    const float* w_x   = (const float*)d_in[5];
    const float* w_h   = (const float*)d_in[6];
    const float* b_x   = (const float*)d_in[7];
    const float* b_h   = (const float*)d_in[8];
    const float* dia_x = (const float*)d_in[9];
    const float* dia_h = (const float*)d_in[10];
    float* out = (float*)d_out;

    float *pP = nullptr, *pGx = nullptr, *pd2x = nullptr;
    cudaGetSymbolAddress((void**)&pP,   g_P);
    cudaGetSymbolAddress((void**)&pGx,  g_Gx);
    cudaGetSymbolAddress((void**)&pd2x, g_d2x);

    // 1) diag corrections + h init
    prep_kernel<<<32, 256>>>(u_x, w_x, dia_x, u_h, w_h, dia_h, h0);

    // 2) P = X @ u_x      (M=16384, N=256, K=1024; B stored [K,N])
    {
        dim3 grid(R / 128, TB / 128);
        gemm_k<false, false><<<grid, 256>>>(x, u_x, pP, TB, R, D,
                                            nullptr, nullptr, nullptr);
    }
    // 3) Gx = P @ w_x^T + x*d2_x + b_x   (M=16384, N=4096, K=256; B stored [N,K])
    {
        dim3 grid(G4H / 128, TB / 128);
        gemm_k<true, true><<<grid, 256>>>(pP, w_x, pGx, TB, G4H, R,
                                          x, pd2x, b_x);
    }
    // 4) persistent recurrence
    cudaFuncSetAttribute(lstm_rec, cudaFuncAttributeMaxDynamicSharedMemorySize,
                         (int)SMEM_BYTES);
    int full_out = (out_size >= T * Bsz * H + 2 * Bsz * H) ? 1 : 0;
    lstm_rec<<<NB, NTH, SMEM_BYTES>>>(c0, h0, u_h, w_h, b_h, out, full_out);
}